// round 5
// baseline (speedup 1.0000x reference)
#include <cuda_runtime.h>
#include <cuda_bf16.h>
#include <cstdint>
#include <cstddef>

#define BB 32
#define TT 512
#define II 512
#define HH 512
#define EE 4
#define GG 2048
#define KKD 1024
#define OUTD 512
#define NED 8
#define NBLK 128
#define NOUT (BB*TT*OUTD)

// ---------------- device scratch ----------------
__device__ float d_rin[BB*II];
__device__ float d_rh [BB*II];
__device__ int   d_ne[EE];
__device__ int   d_rows[EE][BB];
__device__ int   d_selE[BB][2];
__device__ int   d_selSlot[BB][2];
__device__ float d_selW[BB][2];
__device__ float d_lb_dummy[1];

__device__ float d_Wcat[(size_t)NED*16*KKD*128];     // 64 MB  [ed][jblk][k][c]
__device__ float d_bcat[NED*16*128];
__device__ float d_hstate[2*(size_t)NED*BB*HH];      // parity double-buffer
__device__ float d_hout[(size_t)NED*BB*TT*HH];       // 256 MB slotted outputs
__device__ float d_comb[(size_t)BB*TT*2*HH];         // 64 MB
__device__ unsigned d_sync[NED*32];

__device__ __forceinline__ float fsig(float x)  { return 1.f/(1.f+__expf(-x)); }
__device__ __forceinline__ float ftanh(float x) { float e=__expf(2.f*x); return 1.f - 2.f/(e+1.f); }

__device__ __forceinline__ void ffma2(unsigned long long &d, unsigned long long a, unsigned long long b) {
    asm("fma.rn.f32x2 %0, %1, %2, %0;" : "+l"(d) : "l"(a), "l"(b));
}

// ---------------- prep ----------------
__global__ void k_zero() { d_sync[threadIdx.x] = 0u; }

__global__ void k_wcat(const float* __restrict__ Wih, const float* __restrict__ Whh) {
    int idx = blockIdx.x*256 + threadIdx.x;     // 16,777,216
    int c    = idx & 127;
    int k    = (idx >> 7)  & 1023;
    int jblk = (idx >> 17) & 15;
    int ed   = idx >> 21;
    int g = (c >> 5)*512 + jblk*32 + (c & 31);
    float v;
    if (k < 512) v = __ldg(&Wih[((size_t)(ed*GG + g))*512 + k]);
    else         v = __ldg(&Whh[((size_t)(ed*GG + g))*512 + (k-512)]);
    d_Wcat[idx] = v;
}

__global__ void k_bcat(const float* __restrict__ bih, const float* __restrict__ bhh) {
    int idx = blockIdx.x*256 + threadIdx.x;     // 16384
    int c    = idx & 127;
    int jblk = (idx >> 7) & 15;
    int ed   = idx >> 11;
    int g = (c >> 5)*512 + jblk*32 + (c & 31);
    d_bcat[idx] = bih[ed*GG + g] + bhh[ed*GG + g];
}

// ---------------- router ----------------
__global__ void k_mean(const float* __restrict__ x) {
    int b = blockIdx.x, i = threadIdx.x;
    const float* p = x + (size_t)b*TT*II + i;
    float s = 0.f;
    for (int t = 0; t < TT; ++t) s += p[(size_t)t*II];
    d_rin[b*II + i] = s * (1.f/(float)TT);
}

__global__ void k_rh(const float* __restrict__ rW1, const float* __restrict__ rb1) {
    __shared__ float sr[II];
    int b = blockIdx.x, i = threadIdx.x;
    sr[i] = d_rin[b*II + i];
    __syncthreads();
    float s = rb1[i];
    const float* w = rW1 + (size_t)i*II;
    for (int k = 0; k < II; ++k) s += sr[k]*__ldg(&w[k]);
    d_rh[b*II + i] = s / (1.f + expf(-s));
}

__global__ void k_router2(const float* __restrict__ rW2, const float* __restrict__ rb2,
                          float* __restrict__ lb_out) {
    __shared__ float sl[BB][EE];
    __shared__ float sp[BB][EE];
    int tid = threadIdx.x;
    if (tid < BB*EE) {
        int b = tid >> 2, e = tid & 3;
        float s = rb2[e];
        const float* h = d_rh + b*II;
        const float* w = rW2 + e*II;
        for (int k = 0; k < II; ++k) s += h[k]*__ldg(&w[k]);
        sl[b][e] = s;
    }
    __syncthreads();
    if (tid < BB) {
        int b = tid;
        float m = sl[b][0];
        for (int e = 1; e < EE; ++e) m = fmaxf(m, sl[b][e]);
        float p[EE], sum = 0.f;
        for (int e = 0; e < EE; ++e) { p[e] = expf(sl[b][e]-m); sum += p[e]; }
        for (int e = 0; e < EE; ++e) { p[e] /= sum; sp[b][e] = p[e]; }
        int e0 = 0;
        for (int e = 1; e < EE; ++e) if (p[e] > p[e0]) e0 = e;
        int e1 = -1;
        for (int e = 0; e < EE; ++e) { if (e == e0) continue; if (e1 < 0 || p[e] > p[e1]) e1 = e; }
        float z = p[e0] + p[e1];
        d_selE[b][0] = e0; d_selE[b][1] = e1;
        d_selW[b][0] = p[e0]/z; d_selW[b][1] = p[e1]/z;
    }
    __syncthreads();
    if (tid == 0) {
        for (int e = 0; e < EE; ++e) {
            int nn = 0;
            for (int b = 0; b < BB; ++b)
                for (int k = 0; k < 2; ++k)
                    if (d_selE[b][k] == e) { d_rows[e][nn] = b; d_selSlot[b][k] = nn; nn++; }
            d_ne[e] = nn;
        }
        float lb = 0.f;
        for (int e = 0; e < EE; ++e) {
            float u = 0.f;
            for (int b = 0; b < BB; ++b) u += sp[b][e];
            u *= (1.f/(float)BB);
            float dv = u - 1.f/(float)EE;
            lb += dv*dv;
        }
        *lb_out = 0.01f * lb * (1.f/(float)EE);
    }
}

// ---------------- persistent recurrent kernel (FFMA2 + K-split + triple buffer) ----------------
#define CK 16
#define NCHUNK 32     // per kg: 512/CK
// dyn smem: As2[16][2048] dup-pairs | ws[3][2][CK*128] | gs[16][132]
#define SMEM_RECUR ((16*2048 + 3*2*CK*128 + 16*132)*4)

__global__ void __launch_bounds__(256,1) k_recur(const float* __restrict__ x) {
    extern __shared__ float sm[];
    float* As2 = sm;                       // 32768 floats
    float* ws  = sm + 16*2048;             // 12288 floats
    float* gs  = ws + 3*2*CK*128;          // 2112 floats
    __shared__ int sRows[BB];
    __shared__ int sN;

    const int tid = threadIdx.x;
    const int bx  = blockIdx.x;
    const int ed  = bx >> 4;
    const int jblk= bx & 15;
    const int e   = ed >> 1;
    const int dback = ed & 1;

    const int kg   = tid >> 7;            // 0,1  K-half
    const int t128 = tid & 127;
    const int tc = t128 & 31, tr = t128 >> 5;
    const int c0 = tc*4, r0 = tr*4;
    const int j0 = jblk*32;

    if (tid < BB) sRows[tid] = d_rows[e][tid];
    if (tid == 0) sN = d_ne[e];
    __syncthreads();
    const int n = sN;
    if (n == 0) return;
    const int npass = (n + 15) >> 4;

    const float4 biasv = *(const float4*)&d_bcat[(ed*16 + jblk)*128 + c0];
    unsigned long long bias2_0, bias2_1;
    asm("mov.b64 %0, {%1,%2};" : "=l"(bias2_0) : "f"(biasv.x), "f"(biasv.y));
    asm("mov.b64 %0, {%1,%2};" : "=l"(bias2_1) : "f"(biasv.z), "f"(biasv.w));
    const float* Wblk = d_Wcat + (size_t)(ed*16 + jblk)*(KKD*128);

    const int cr = tid >> 4;              // 0..15 cell row
    const int cj = (tid & 15)*2;          // 0..30 cell j-pair
    float creg[2][2] = {{0.f,0.f},{0.f,0.f}};

    unsigned target = 0;
    for (int s = 0; s < TT; ++s) {
        const int t = dback ? (TT-1-s) : s;

        for (int pass = 0; pass < npass; ++pass) {
            const int prows = min(16, n - pass*16);

            // ---- stage A duplicated: x half (k 0..511) ----
            for (int idx = tid; idx < 16*128; idx += 256) {
                int r = idx >> 7, k4 = idx & 127;
                float4 v = make_float4(0.f,0.f,0.f,0.f);
                if (r < prows)
                    v = __ldg((const float4*)&x[((size_t)(sRows[pass*16+r]*TT + t))*II + k4*4]);
                float* dst = &As2[r*2048 + k4*8];
                *(float4*)dst     = make_float4(v.x,v.x,v.y,v.y);
                *(float4*)(dst+4) = make_float4(v.z,v.z,v.w,v.w);
            }
            // ---- stage A duplicated: h half (k 512..1023) ----
            if (s == 0) {
                for (int idx = tid; idx < 16*128; idx += 256) {
                    int r = idx >> 7, k4 = idx & 127;
                    float* dst = &As2[r*2048 + 1024 + k4*8];
                    *(float4*)dst     = make_float4(0.f,0.f,0.f,0.f);
                    *(float4*)(dst+4) = make_float4(0.f,0.f,0.f,0.f);
                }
            } else {
                const float* hsrc = d_hstate + (size_t)((s&1)^1)*(NED*BB*HH) + (size_t)ed*(BB*HH);
                for (int idx = tid; idx < 16*128; idx += 256) {
                    int r = idx >> 7, k4 = idx & 127;
                    float4 v = make_float4(0.f,0.f,0.f,0.f);
                    if (r < prows)
                        v = __ldcg((const float4*)&hsrc[(pass*16+r)*HH + k4*4]);
                    float* dst = &As2[r*2048 + 1024 + k4*8];
                    *(float4*)dst     = make_float4(v.x,v.x,v.y,v.y);
                    *(float4*)(dst+4) = make_float4(v.z,v.z,v.w,v.w);
                }
            }
            // ---- stage W chunks 0,1 + prefetch chunk 2 ----
            {
                const float4* s0 = (const float4*)(Wblk + (size_t)(kg*512 + 0*CK)*128);
                const float4* s1 = (const float4*)(Wblk + (size_t)(kg*512 + 1*CK)*128);
                float4* b0 = (float4*)(ws + (0*2+kg)*(CK*128));
                float4* b1 = (float4*)(ws + (1*2+kg)*(CK*128));
                #pragma unroll
                for (int j = 0; j < 4; ++j) b0[t128 + j*128] = __ldcg(s0 + t128 + j*128);
                #pragma unroll
                for (int j = 0; j < 4; ++j) b1[t128 + j*128] = __ldcg(s1 + t128 + j*128);
            }
            float4 pf[4];
            {
                const float4* s2 = (const float4*)(Wblk + (size_t)(kg*512 + 2*CK)*128);
                #pragma unroll
                for (int j = 0; j < 4; ++j) pf[j] = __ldcg(s2 + t128 + j*128);
            }
            __syncthreads();

            unsigned long long acc[4][2];
            #pragma unroll
            for (int i = 0; i < 4; ++i) {
                acc[i][0] = (kg == 0) ? bias2_0 : 0ull;
                acc[i][1] = (kg == 0) ? bias2_1 : 0ull;
            }
            const bool rowAct = (r0 < prows);

            #pragma unroll 1
            for (int ch = 0; ch < NCHUNK; ++ch) {
                const float* wb = ws + ((ch % 3)*2 + kg)*(CK*128);
                if (rowAct) {
                    const int kglob0 = kg*512 + ch*CK;
                    #pragma unroll
                    for (int kk = 0; kk < CK; kk += 2) {
                        ulonglong2 wk  = *(const ulonglong2*)&wb[(kk  )*128 + c0];
                        ulonglong2 wk1 = *(const ulonglong2*)&wb[(kk+1)*128 + c0];
                        #pragma unroll
                        for (int i = 0; i < 4; ++i) {
                            ulonglong2 A2 = *(const ulonglong2*)&As2[(r0+i)*2048 + (kglob0+kk)*2];
                            ffma2(acc[i][0], A2.x, wk.x);
                            ffma2(acc[i][1], A2.x, wk.y);
                            ffma2(acc[i][0], A2.y, wk1.x);
                            ffma2(acc[i][1], A2.y, wk1.y);
                        }
                    }
                }
                if (ch + 2 < NCHUNK) {
                    float4* dst = (float4*)(ws + (((ch+2) % 3)*2 + kg)*(CK*128));
                    #pragma unroll
                    for (int j = 0; j < 4; ++j) dst[t128 + j*128] = pf[j];
                }
                if (ch + 3 < NCHUNK) {
                    const float4* src = (const float4*)(Wblk + (size_t)(kg*512 + (ch+3)*CK)*128);
                    #pragma unroll
                    for (int j = 0; j < 4; ++j) pf[j] = __ldcg(src + t128 + j*128);
                }
                __syncthreads();
            }

            // ---- reduce kg partials into gs ----
            if (kg == 1 && rowAct) {
                #pragma unroll
                for (int i = 0; i < 4; ++i) {
                    *(unsigned long long*)&gs[(r0+i)*132 + c0    ] = acc[i][0];
                    *(unsigned long long*)&gs[(r0+i)*132 + c0 + 2] = acc[i][1];
                }
            }
            __syncthreads();
            if (kg == 0 && rowAct) {
                #pragma unroll
                for (int i = 0; i < 4; ++i) {
                    unsigned long long p0 = *(unsigned long long*)&gs[(r0+i)*132 + c0];
                    unsigned long long p1 = *(unsigned long long*)&gs[(r0+i)*132 + c0 + 2];
                    unsigned long long s0, s1;
                    asm("add.rn.f32x2 %0, %1, %2;" : "=l"(s0) : "l"(acc[i][0]), "l"(p0));
                    asm("add.rn.f32x2 %0, %1, %2;" : "=l"(s1) : "l"(acc[i][1]), "l"(p1));
                    *(unsigned long long*)&gs[(r0+i)*132 + c0    ] = s0;
                    *(unsigned long long*)&gs[(r0+i)*132 + c0 + 2] = s1;
                }
            }
            __syncthreads();

            // ---- LSTM cell update (c in regs) ----
            if (cr < prows) {
                float hv[2];
                #pragma unroll
                for (int v2 = 0; v2 < 2; ++v2) {
                    int jj = cj + v2;
                    float ig = fsig (gs[cr*132 +      jj]);
                    float fg = fsig (gs[cr*132 + 32 + jj]);
                    float gg = ftanh(gs[cr*132 + 64 + jj]);
                    float og = fsig (gs[cr*132 + 96 + jj]);
                    float c = fg*creg[pass][v2] + ig*gg;
                    creg[pass][v2] = c;
                    hv[v2] = og * ftanh(c);
                }
                float2 h2 = make_float2(hv[0], hv[1]);
                __stcg((float2*)&d_hstate[(size_t)(s&1)*(NED*BB*HH) + (size_t)ed*(BB*HH)
                                          + (pass*16+cr)*HH + j0 + cj], h2);
                __stcg((float2*)&d_hout[(((size_t)(ed*BB + pass*16 + cr))*TT + t)*HH + j0 + cj], h2);
            }
            __syncthreads();
        } // pass

        // ---- per-(e,d) grid barrier ----
        __threadfence();
        __syncthreads();
        target += 16;
        if (tid == 0) {
            asm volatile("red.release.gpu.global.add.u32 [%0], %1;" :: "l"(d_sync + ed*32), "r"(1u) : "memory");
            unsigned v;
            do {
                asm volatile("ld.acquire.gpu.global.u32 %0, [%1];" : "=r"(v) : "l"(d_sync + ed*32) : "memory");
            } while (v < target);
        }
        __syncthreads();
    }
}

// ---------------- combine ----------------
__global__ void k_combine() {
    int idx = blockIdx.x*256 + threadIdx.x;   // 4,194,304 float4s
    int dj4 = idx & 255;
    int t   = (idx >> 8) & 511;
    int b   = idx >> 17;
    int d   = dj4 >> 7;
    int j4  = dj4 & 127;
    float w0 = d_selW[b][0], w1 = d_selW[b][1];
    int e0 = d_selE[b][0],   e1 = d_selE[b][1];
    int s0 = d_selSlot[b][0], s1 = d_selSlot[b][1];
    float4 h0 = *(const float4*)&d_hout[(((size_t)((e0*2+d)*BB + s0))*TT + t)*HH + j4*4];
    float4 h1 = *(const float4*)&d_hout[(((size_t)((e1*2+d)*BB + s1))*TT + t)*HH + j4*4];
    float4 r;
    r.x = w0*h0.x + w1*h1.x; r.y = w0*h0.y + w1*h1.y;
    r.z = w0*h0.z + w1*h1.z; r.w = w0*h0.w + w1*h1.w;
    ((float4*)d_comb)[idx] = r;
}

// ---------------- out GEMM ----------------
__global__ void __launch_bounds__(256) k_outgemm(float* __restrict__ out,
                                                 const float* __restrict__ Wout,
                                                 const float* __restrict__ bout) {
    __shared__ float As[16][68];
    __shared__ float Bs[16][68];
    const int tid = threadIdx.x;
    const int m0 = blockIdx.y*64;
    const int n0 = blockIdx.x*64;
    const int tm = tid >> 4, tn = tid & 15;
    float acc[4][4] = {};
    const int r = tid >> 2, q = tid & 3;
    for (int kc = 0; kc < KKD; kc += 16) {
        float4 a = *(const float4*)&d_comb[(size_t)(m0+r)*KKD + kc + q*4];
        As[q*4+0][r]=a.x; As[q*4+1][r]=a.y; As[q*4+2][r]=a.z; As[q*4+3][r]=a.w;
        float4 bb = __ldg((const float4*)&Wout[(size_t)(n0+r)*KKD + kc + q*4]);
        Bs[q*4+0][r]=bb.x; Bs[q*4+1][r]=bb.y; Bs[q*4+2][r]=bb.z; Bs[q*4+3][r]=bb.w;
        __syncthreads();
        #pragma unroll
        for (int k = 0; k < 16; ++k) {
            float4 av = *(const float4*)&As[k][tm*4];
            float4 bv = *(const float4*)&Bs[k][tn*4];
            acc[0][0]+=av.x*bv.x; acc[0][1]+=av.x*bv.y; acc[0][2]+=av.x*bv.z; acc[0][3]+=av.x*bv.w;
            acc[1][0]+=av.y*bv.x; acc[1][1]+=av.y*bv.y; acc[1][2]+=av.y*bv.z; acc[1][3]+=av.y*bv.w;
            acc[2][0]+=av.z*bv.x; acc[2][1]+=av.z*bv.y; acc[2][2]+=av.z*bv.z; acc[2][3]+=av.z*bv.w;
            acc[3][0]+=av.w*bv.x; acc[3][1]+=av.w*bv.y; acc[3][2]+=av.w*bv.z; acc[3][3]+=av.w*bv.w;
        }
        __syncthreads();
    }
    float4 bv = *(const float4*)&bout[n0 + tn*4];
    #pragma unroll
    for (int i = 0; i < 4; ++i) {
        float4 o;
        o.x = acc[i][0]+bv.x; o.y = acc[i][1]+bv.y; o.z = acc[i][2]+bv.z; o.w = acc[i][3]+bv.w;
        *(float4*)&out[(size_t)(m0+tm*4+i)*OUTD + n0 + tn*4] = o;
    }
}

// ---------------- launch ----------------
extern "C" void kernel_launch(void* const* d_in, const int* in_sizes, int n_in,
                              void* d_out, int out_size) {
    const float* x    = (const float*)d_in[0];
    const float* rW1  = (const float*)d_in[1];
    const float* rb1  = (const float*)d_in[2];
    const float* rW2  = (const float*)d_in[3];
    const float* rb2  = (const float*)d_in[4];
    const float* Wih  = (const float*)d_in[5];
    const float* Whh  = (const float*)d_in[6];
    const float* bih  = (const float*)d_in[7];
    const float* bhh  = (const float*)d_in[8];
    const float* Wout = (const float*)d_in[9];
    const float* bout = (const float*)d_in[10];
    float* out = (float*)d_out;

    float* lbdst;
    if (out_size > NOUT) {
        lbdst = out + NOUT;
    } else {
        cudaGetSymbolAddress((void**)&lbdst, d_lb_dummy);
    }

    static bool attrDone = false;
    if (!attrDone) {
        cudaFuncSetAttribute(k_recur, cudaFuncAttributeMaxDynamicSharedMemorySize, SMEM_RECUR);
        attrDone = true;
    }

    k_zero<<<1, NED*32>>>();
    k_wcat<<<65536, 256>>>(Wih, Whh);
    k_bcat<<<64, 256>>>(bih, bhh);
    k_mean<<<BB, II>>>(x);
    k_rh<<<BB, II>>>(rW1, rb1);
    k_router2<<<1, 128>>>(rW2, rb2, lbdst);
    k_recur<<<NBLK, 256, SMEM_RECUR>>>(x);
    k_combine<<<16384, 256>>>();
    dim3 g(OUTD/64, (BB*TT)/64);
    k_outgemm<<<g, 256>>>(out, Wout, bout);
}

// round 6
// speedup vs baseline: 1.8757x; 1.8757x over previous
#include <cuda_runtime.h>
#include <cuda_bf16.h>
#include <cstdint>
#include <cstddef>

#define BB 32
#define TT 512
#define II 512
#define HH 512
#define EE 4
#define GG 2048
#define KKD 1024
#define OUTD 512
#define NED 8
#define NBLK 128
#define NOUT (BB*TT*OUTD)

// ---------------- device scratch ----------------
__device__ float d_rin[BB*II];
__device__ float d_rh [BB*II];
__device__ int   d_ne[EE];
__device__ int   d_rows[EE][BB];
__device__ int   d_selE[BB][2];
__device__ int   d_selSlot[BB][2];
__device__ float d_selW[BB][2];
__device__ float d_lb_dummy[1];

__device__ float d_Whhp[(size_t)NED*16*512*128];     // 32 MB  [ed][jblk][k<512][c<128]
__device__ float d_Wihp[(size_t)EE*512*4096];        // 32 MB  [e][k<512][gp<4096]
__device__ float d_bcat[NED*16*128];
__device__ float d_xp[(size_t)EE*32*TT*4096];        // 1.07 GB [e][slot<32][t][gp]
__device__ float d_hstate[2*(size_t)NED*BB*HH];      // parity double-buffer
__device__ float d_hout[(size_t)NED*BB*TT*HH];       // 256 MB slotted outputs
__device__ float d_comb[(size_t)BB*TT*2*HH];         // 64 MB
__device__ unsigned d_sync[NED*32];

__device__ __forceinline__ float fsig(float x)  { return 1.f/(1.f+__expf(-x)); }
__device__ __forceinline__ float ftanh(float x) { float e=__expf(2.f*x); return 1.f - 2.f/(e+1.f); }

__device__ __forceinline__ void ffma2(unsigned long long &d, unsigned long long a, unsigned long long b) {
    asm("fma.rn.f32x2 %0, %1, %2, %0;" : "+l"(d) : "l"(a), "l"(b));
}

// ---------------- prep ----------------
__global__ void k_zero() { d_sync[threadIdx.x] = 0u; }

// Whhp[ed][jblk][k][c], c=q*32+jj -> gate g = q*512 + jblk*32 + jj
__global__ void k_whhp(const float* __restrict__ Whh) {
    int idx = blockIdx.x*256 + threadIdx.x;     // 8,388,608
    int c    = idx & 127;
    int k    = (idx >> 7)  & 511;
    int jblk = (idx >> 16) & 15;
    int ed   = idx >> 20;
    int g = (c >> 5)*512 + jblk*32 + (c & 31);
    d_Whhp[idx] = __ldg(&Whh[((size_t)(ed*GG + g))*512 + k]);
}

// Wihp[e][k][gp], gp = d*2048 + jblk*128 + q*32 + jj  -> g = q*512 + jblk*32 + jj
__global__ void k_wihp(const float* __restrict__ Wih) {
    int idx = blockIdx.x*256 + threadIdx.x;     // 8,388,608
    int gp = idx & 4095;
    int k  = (idx >> 12) & 511;
    int e  = idx >> 21;
    int d    = gp >> 11;
    int rem  = gp & 2047;
    int jblk = rem >> 7;
    int c    = rem & 127;
    int g = (c >> 5)*512 + jblk*32 + (c & 31);
    d_Wihp[idx] = __ldg(&Wih[((size_t)((e*2 + d)*GG + g))*512 + k]);
}

__global__ void k_bcat(const float* __restrict__ bih, const float* __restrict__ bhh) {
    int idx = blockIdx.x*256 + threadIdx.x;     // 16384
    int c    = idx & 127;
    int jblk = (idx >> 7) & 15;
    int ed   = idx >> 11;
    int g = (c >> 5)*512 + jblk*32 + (c & 31);
    d_bcat[idx] = bih[ed*GG + g] + bhh[ed*GG + g];
}

// ---------------- router ----------------
__global__ void k_mean(const float* __restrict__ x) {
    int b = blockIdx.x, i = threadIdx.x;
    const float* p = x + (size_t)b*TT*II + i;
    float s = 0.f;
    for (int t = 0; t < TT; ++t) s += p[(size_t)t*II];
    d_rin[b*II + i] = s * (1.f/(float)TT);
}

__global__ void k_rh(const float* __restrict__ rW1, const float* __restrict__ rb1) {
    __shared__ float sr[II];
    int b = blockIdx.x, i = threadIdx.x;
    sr[i] = d_rin[b*II + i];
    __syncthreads();
    float s = rb1[i];
    const float* w = rW1 + (size_t)i*II;
    for (int k = 0; k < II; ++k) s += sr[k]*__ldg(&w[k]);
    d_rh[b*II + i] = s / (1.f + expf(-s));
}

__global__ void k_router2(const float* __restrict__ rW2, const float* __restrict__ rb2,
                          float* __restrict__ lb_out) {
    __shared__ float sl[BB][EE];
    __shared__ float sp[BB][EE];
    int tid = threadIdx.x;
    if (tid < BB*EE) {
        int b = tid >> 2, e = tid & 3;
        float s = rb2[e];
        const float* h = d_rh + b*II;
        const float* w = rW2 + e*II;
        for (int k = 0; k < II; ++k) s += h[k]*__ldg(&w[k]);
        sl[b][e] = s;
    }
    __syncthreads();
    if (tid < BB) {
        int b = tid;
        float m = sl[b][0];
        for (int e = 1; e < EE; ++e) m = fmaxf(m, sl[b][e]);
        float p[EE], sum = 0.f;
        for (int e = 0; e < EE; ++e) { p[e] = expf(sl[b][e]-m); sum += p[e]; }
        for (int e = 0; e < EE; ++e) { p[e] /= sum; sp[b][e] = p[e]; }
        int e0 = 0;
        for (int e = 1; e < EE; ++e) if (p[e] > p[e0]) e0 = e;
        int e1 = -1;
        for (int e = 0; e < EE; ++e) { if (e == e0) continue; if (e1 < 0 || p[e] > p[e1]) e1 = e; }
        float z = p[e0] + p[e1];
        d_selE[b][0] = e0; d_selE[b][1] = e1;
        d_selW[b][0] = p[e0]/z; d_selW[b][1] = p[e1]/z;
    }
    __syncthreads();
    if (tid == 0) {
        for (int e = 0; e < EE; ++e) {
            int nn = 0;
            for (int b = 0; b < BB; ++b)
                for (int k = 0; k < 2; ++k)
                    if (d_selE[b][k] == e) { d_rows[e][nn] = b; d_selSlot[b][k] = nn; nn++; }
            d_ne[e] = nn;
            for (int r = nn; r < BB; ++r) d_rows[e][r] = 0;
        }
        float lb = 0.f;
        for (int e = 0; e < EE; ++e) {
            float u = 0.f;
            for (int b = 0; b < BB; ++b) u += sp[b][e];
            u *= (1.f/(float)BB);
            float dv = u - 1.f/(float)EE;
            lb += dv*dv;
        }
        *lb_out = 0.01f * lb * (1.f/(float)EE);
    }
}

// ---------------- xp GEMM: xp[e][r][t][gp] = x_row @ Wihp  (FFMA2, 128x128 tile) ----------------
__global__ void __launch_bounds__(256,2) k_xp(const float* __restrict__ x) {
    __shared__ float As2[8*256];   // A duplicated: As2[k][2m],[2m+1]
    __shared__ float Bs [8*128];   // B natural:    Bs[k][n]
    const int e  = blockIdx.z;
    const int r  = blockIdx.y >> 2;
    if (r >= d_ne[e]) return;
    const int t0 = (blockIdx.y & 3)*128;
    const int n0 = blockIdx.x*128;
    const int tid = threadIdx.x;
    const int b = d_rows[e][r];

    const float* Arow = x + ((size_t)b*TT + t0)*II;          // A[m][k] = Arow[m*512+k]
    const float* Bmat = d_Wihp + (size_t)e*512*4096 + n0;    // B[k][n] = Bmat[k*4096+n]

    const int i0 = (tid >> 4)*8;
    const int j0 = (tid & 15)*8;

    unsigned long long acc2[8][4];
    #pragma unroll
    for (int i = 0; i < 8; ++i)
        #pragma unroll
        for (int j = 0; j < 4; ++j) acc2[i][j] = 0ull;

    const int sm = tid >> 1, skq = tid & 1;
    const int bk = tid >> 5, bn = (tid & 31)*4;

    for (int kc = 0; kc < 512; kc += 8) {
        // stage A duplicated (transpose k-major)
        {
            float4 v = *(const float4*)&Arow[(size_t)sm*II + kc + skq*4];
            float* dst = &As2[(skq*4)*256 + 2*sm];
            *(float2*)(dst        ) = make_float2(v.x, v.x);
            *(float2*)(dst + 256  ) = make_float2(v.y, v.y);
            *(float2*)(dst + 512  ) = make_float2(v.z, v.z);
            *(float2*)(dst + 768  ) = make_float2(v.w, v.w);
        }
        // stage B
        {
            float4 v = __ldg((const float4*)&Bmat[(size_t)(kc + bk)*4096 + bn]);
            *(float4*)&Bs[bk*128 + bn] = v;
        }
        __syncthreads();
        #pragma unroll
        for (int k = 0; k < 8; ++k) {
            ulonglong2 a01 = *(const ulonglong2*)&As2[k*256 + i0*2];
            ulonglong2 a23 = *(const ulonglong2*)&As2[k*256 + i0*2 + 4];
            ulonglong2 a45 = *(const ulonglong2*)&As2[k*256 + i0*2 + 8];
            ulonglong2 a67 = *(const ulonglong2*)&As2[k*256 + i0*2 + 12];
            ulonglong2 b01 = *(const ulonglong2*)&Bs[k*128 + j0];
            ulonglong2 b23 = *(const ulonglong2*)&Bs[k*128 + j0 + 4];
            ffma2(acc2[0][0], a01.x, b01.x); ffma2(acc2[0][1], a01.x, b01.y);
            ffma2(acc2[0][2], a01.x, b23.x); ffma2(acc2[0][3], a01.x, b23.y);
            ffma2(acc2[1][0], a01.y, b01.x); ffma2(acc2[1][1], a01.y, b01.y);
            ffma2(acc2[1][2], a01.y, b23.x); ffma2(acc2[1][3], a01.y, b23.y);
            ffma2(acc2[2][0], a23.x, b01.x); ffma2(acc2[2][1], a23.x, b01.y);
            ffma2(acc2[2][2], a23.x, b23.x); ffma2(acc2[2][3], a23.x, b23.y);
            ffma2(acc2[3][0], a23.y, b01.x); ffma2(acc2[3][1], a23.y, b01.y);
            ffma2(acc2[3][2], a23.y, b23.x); ffma2(acc2[3][3], a23.y, b23.y);
            ffma2(acc2[4][0], a45.x, b01.x); ffma2(acc2[4][1], a45.x, b01.y);
            ffma2(acc2[4][2], a45.x, b23.x); ffma2(acc2[4][3], a45.x, b23.y);
            ffma2(acc2[5][0], a45.y, b01.x); ffma2(acc2[5][1], a45.y, b01.y);
            ffma2(acc2[5][2], a45.y, b23.x); ffma2(acc2[5][3], a45.y, b23.y);
            ffma2(acc2[6][0], a67.x, b01.x); ffma2(acc2[6][1], a67.x, b01.y);
            ffma2(acc2[6][2], a67.x, b23.x); ffma2(acc2[6][3], a67.x, b23.y);
            ffma2(acc2[7][0], a67.y, b01.x); ffma2(acc2[7][1], a67.y, b01.y);
            ffma2(acc2[7][2], a67.y, b23.x); ffma2(acc2[7][3], a67.y, b23.y);
        }
        __syncthreads();
    }

    float* xpd = d_xp + (((size_t)e*32 + r)*TT)*4096 + n0 + j0;
    #pragma unroll
    for (int i = 0; i < 8; ++i) {
        float2 p0 = *(float2*)&acc2[i][0];
        float2 p1 = *(float2*)&acc2[i][1];
        float2 p2 = *(float2*)&acc2[i][2];
        float2 p3 = *(float2*)&acc2[i][3];
        float* dst = xpd + (size_t)(t0 + i0 + i)*4096;
        *(float4*)(dst    ) = make_float4(p0.x, p0.y, p1.x, p1.y);
        *(float4*)(dst + 4) = make_float4(p2.x, p2.y, p3.x, p3.y);
    }
}

// ---------------- persistent recurrent kernel (K=512, R3-proven inner loop) ----------------
// dyn smem: As[32][512] | ws[2][4096] | gs[32*136]
#define SMEM_RECUR ((32*512 + 2*4096 + 32*136)*4)
#define NCH 16

__global__ void __launch_bounds__(256,1) k_recur() {
    extern __shared__ float sm[];
    float* As = sm;                    // 16384 floats
    float* ws = sm + 32*512;           // 8192 floats
    float* gs = ws + 2*4096;           // 4352 floats
    __shared__ int sN;

    const int tid  = threadIdx.x;
    const int bx   = blockIdx.x;
    const int ed   = bx >> 4;
    const int jblk = bx & 15;
    const int e    = ed >> 1;
    const int dback= ed & 1;
    const int tc = tid & 31, tr = tid >> 5;
    const int c0 = tc*4,     r0 = tr*4;
    const int j0 = jblk*32;

    if (tid == 0) sN = d_ne[e];
    __syncthreads();
    const int n = sN;
    if (n == 0) return;
    const bool rowActive = (r0 < n);

    const float4 biasv = *(const float4*)&d_bcat[(ed*16 + jblk)*128 + c0];
    const float* Wblk = d_Whhp + (size_t)(ed*16 + jblk)*(512*128);
    const float* xpB  = d_xp + (size_t)e*32*TT*4096 + (size_t)dback*2048 + (size_t)jblk*128 + c0;

    const int cr  = tid >> 3;
    const int cj0 = (tid & 7)*4;
    const bool cellActive = (cr < n);
    float creg[4] = {0.f, 0.f, 0.f, 0.f};

    unsigned target = 0;
    for (int s = 0; s < TT; ++s) {
        const int t = dback ? (TT-1-s) : s;

        // ---- stage A = h_prev ----
        if (s == 0) {
            for (int idx = tid; idx < n*128; idx += 256)
                ((float4*)As)[idx] = make_float4(0.f,0.f,0.f,0.f);
        } else {
            const float* hsrc = d_hstate + (size_t)((s&1)^1)*(NED*BB*HH) + (size_t)ed*(BB*HH);
            for (int idx = tid; idx < n*128; idx += 256)
                ((float4*)As)[idx] = __ldcg((const float4*)hsrc + idx);
        }
        // stage W chunk 0
        {
            const float4* src = (const float4*)Wblk;
            float4* dst = (float4*)ws;
            dst[tid]     = __ldcg(src+tid);     dst[tid+256] = __ldcg(src+tid+256);
            dst[tid+512] = __ldcg(src+tid+512); dst[tid+768] = __ldcg(src+tid+768);
        }
        __syncthreads();

        float acc[4][4];
        if (rowActive) {
            #pragma unroll
            for (int i = 0; i < 4; ++i) {
                float4 xv = __ldcg((const float4*)(xpB + (((size_t)(r0+i)*TT + t)*4096)));
                acc[i][0] = biasv.x + xv.x; acc[i][1] = biasv.y + xv.y;
                acc[i][2] = biasv.z + xv.z; acc[i][3] = biasv.w + xv.w;
            }
        }

        int cur = 0;
        #pragma unroll 1
        for (int kc = 0; kc < NCH; ++kc) {
            float4 pf0, pf1, pf2, pf3;
            if (kc < NCH-1) {
                const float4* src = (const float4*)(Wblk + (size_t)(kc+1)*4096);
                pf0 = __ldcg(src+tid);     pf1 = __ldcg(src+tid+256);
                pf2 = __ldcg(src+tid+512); pf3 = __ldcg(src+tid+768);
            }
            if (rowActive) {
                const float* wsc = ws + cur*4096;
                #pragma unroll
                for (int kk = 0; kk < 32; kk += 4) {
                    const int kb = kc*32 + kk;
                    float4 a0 = *(const float4*)&As[(r0+0)*512 + kb];
                    float4 a1 = *(const float4*)&As[(r0+1)*512 + kb];
                    float4 a2 = *(const float4*)&As[(r0+2)*512 + kb];
                    float4 a3 = *(const float4*)&As[(r0+3)*512 + kb];
                    #pragma unroll
                    for (int u = 0; u < 4; ++u) {
                        float4 w = *(const float4*)&wsc[(kk+u)*128 + c0];
                        float av0 = (&a0.x)[u], av1 = (&a1.x)[u], av2 = (&a2.x)[u], av3 = (&a3.x)[u];
                        acc[0][0] += av0*w.x; acc[0][1] += av0*w.y; acc[0][2] += av0*w.z; acc[0][3] += av0*w.w;
                        acc[1][0] += av1*w.x; acc[1][1] += av1*w.y; acc[1][2] += av1*w.z; acc[1][3] += av1*w.w;
                        acc[2][0] += av2*w.x; acc[2][1] += av2*w.y; acc[2][2] += av2*w.z; acc[2][3] += av2*w.w;
                        acc[3][0] += av3*w.x; acc[3][1] += av3*w.y; acc[3][2] += av3*w.z; acc[3][3] += av3*w.w;
                    }
                }
            }
            __syncthreads();
            if (kc < NCH-1) {
                float4* dst = (float4*)(ws + (cur^1)*4096);
                dst[tid] = pf0; dst[tid+256] = pf1; dst[tid+512] = pf2; dst[tid+768] = pf3;
            }
            __syncthreads();
            cur ^= 1;
        }

        // ---- exchange gates ----
        if (rowActive) {
            #pragma unroll
            for (int i = 0; i < 4; ++i)
                *(float4*)&gs[(r0+i)*136 + c0] = make_float4(acc[i][0],acc[i][1],acc[i][2],acc[i][3]);
        }
        __syncthreads();

        // ---- cell update ----
        if (cellActive) {
            float hv[4];
            #pragma unroll
            for (int v = 0; v < 4; ++v) {
                int jj = cj0 + v;
                float ig = fsig (gs[cr*136 +      jj]);
                float fg = fsig (gs[cr*136 + 32 + jj]);
                float gg = ftanh(gs[cr*136 + 64 + jj]);
                float og = fsig (gs[cr*136 + 96 + jj]);
                float c = fg*creg[v] + ig*gg;
                creg[v] = c;
                hv[v] = og * ftanh(c);
            }
            float4 h4 = make_float4(hv[0],hv[1],hv[2],hv[3]);
            __stcg((float4*)&d_hstate[(size_t)(s&1)*(NED*BB*HH) + (size_t)ed*(BB*HH) + cr*HH + j0 + cj0], h4);
            __stcg((float4*)&d_hout[(((size_t)(ed*BB + cr))*TT + t)*HH + j0 + cj0], h4);
        }
        __threadfence();
        __syncthreads();

        // ---- per-(e,d) grid barrier ----
        target += 16;
        if (tid == 0) {
            asm volatile("red.release.gpu.global.add.u32 [%0], %1;" :: "l"(d_sync + ed*32), "r"(1u) : "memory");
            unsigned v;
            do {
                asm volatile("ld.acquire.gpu.global.u32 %0, [%1];" : "=r"(v) : "l"(d_sync + ed*32) : "memory");
            } while (v < target);
        }
        __syncthreads();
    }
}

// ---------------- combine ----------------
__global__ void k_combine() {
    int idx = blockIdx.x*256 + threadIdx.x;   // 4,194,304 float4s
    int dj4 = idx & 255;
    int t   = (idx >> 8) & 511;
    int b   = idx >> 17;
    int d   = dj4 >> 7;
    int j4  = dj4 & 127;
    float w0 = d_selW[b][0], w1 = d_selW[b][1];
    int e0 = d_selE[b][0],   e1 = d_selE[b][1];
    int s0 = d_selSlot[b][0], s1 = d_selSlot[b][1];
    float4 h0 = *(const float4*)&d_hout[(((size_t)((e0*2+d)*BB + s0))*TT + t)*HH + j4*4];
    float4 h1 = *(const float4*)&d_hout[(((size_t)((e1*2+d)*BB + s1))*TT + t)*HH + j4*4];
    float4 r;
    r.x = w0*h0.x + w1*h1.x; r.y = w0*h0.y + w1*h1.y;
    r.z = w0*h0.z + w1*h1.z; r.w = w0*h0.w + w1*h1.w;
    ((float4*)d_comb)[idx] = r;
}

// ---------------- out GEMM ----------------
__global__ void __launch_bounds__(256) k_outgemm(float* __restrict__ out,
                                                 const float* __restrict__ Wout,
                                                 const float* __restrict__ bout) {
    __shared__ float As[16][68];
    __shared__ float Bs[16][68];
    const int tid = threadIdx.x;
    const int m0 = blockIdx.y*64;
    const int n0 = blockIdx.x*64;
    const int tm = tid >> 4, tn = tid & 15;
    float acc[4][4] = {};
    const int r = tid >> 2, q = tid & 3;
    for (int kc = 0; kc < KKD; kc += 16) {
        float4 a = *(const float4*)&d_comb[(size_t)(m0+r)*KKD + kc + q*4];
        As[q*4+0][r]=a.x; As[q*4+1][r]=a.y; As[q*4+2][r]=a.z; As[q*4+3][r]=a.w;
        float4 bb = __ldg((const float4*)&Wout[(size_t)(n0+r)*KKD + kc + q*4]);
        Bs[q*4+0][r]=bb.x; Bs[q*4+1][r]=bb.y; Bs[q*4+2][r]=bb.z; Bs[q*4+3][r]=bb.w;
        __syncthreads();
        #pragma unroll
        for (int k = 0; k < 16; ++k) {
            float4 av = *(const float4*)&As[k][tm*4];
            float4 bv = *(const float4*)&Bs[k][tn*4];
            acc[0][0]+=av.x*bv.x; acc[0][1]+=av.x*bv.y; acc[0][2]+=av.x*bv.z; acc[0][3]+=av.x*bv.w;
            acc[1][0]+=av.y*bv.x; acc[1][1]+=av.y*bv.y; acc[1][2]+=av.y*bv.z; acc[1][3]+=av.y*bv.w;
            acc[2][0]+=av.z*bv.x; acc[2][1]+=av.z*bv.y; acc[2][2]+=av.z*bv.z; acc[2][3]+=av.z*bv.w;
            acc[3][0]+=av.w*bv.x; acc[3][1]+=av.w*bv.y; acc[3][2]+=av.w*bv.z; acc[3][3]+=av.w*bv.w;
        }
        __syncthreads();
    }
    float4 bv = *(const float4*)&bout[n0 + tn*4];
    #pragma unroll
    for (int i = 0; i < 4; ++i) {
        float4 o;
        o.x = acc[i][0]+bv.x; o.y = acc[i][1]+bv.y; o.z = acc[i][2]+bv.z; o.w = acc[i][3]+bv.w;
        *(float4*)&out[(size_t)(m0+tm*4+i)*OUTD + n0 + tn*4] = o;
    }
}

// ---------------- launch ----------------
extern "C" void kernel_launch(void* const* d_in, const int* in_sizes, int n_in,
                              void* d_out, int out_size) {
    const float* x    = (const float*)d_in[0];
    const float* rW1  = (const float*)d_in[1];
    const float* rb1  = (const float*)d_in[2];
    const float* rW2  = (const float*)d_in[3];
    const float* rb2  = (const float*)d_in[4];
    const float* Wih  = (const float*)d_in[5];
    const float* Whh  = (const float*)d_in[6];
    const float* bih  = (const float*)d_in[7];
    const float* bhh  = (const float*)d_in[8];
    const float* Wout = (const float*)d_in[9];
    const float* bout = (const float*)d_in[10];
    float* out = (float*)d_out;

    float* lbdst;
    if (out_size > NOUT) {
        lbdst = out + NOUT;
    } else {
        cudaGetSymbolAddress((void**)&lbdst, d_lb_dummy);
    }

    static bool attrDone = false;
    if (!attrDone) {
        cudaFuncSetAttribute(k_recur, cudaFuncAttributeMaxDynamicSharedMemorySize, SMEM_RECUR);
        attrDone = true;
    }

    k_zero<<<1, NED*32>>>();
    k_whhp<<<32768, 256>>>(Whh);
    k_wihp<<<32768, 256>>>(Wih);
    k_bcat<<<64, 256>>>(bih, bhh);
    k_mean<<<BB, II>>>(x);
    k_rh<<<BB, II>>>(rW1, rb1);
    k_router2<<<1, 128>>>(rW2, rb2, lbdst);
    k_xp<<<dim3(32, 128, EE), 256>>>(x);
    k_recur<<<NBLK, 256, SMEM_RECUR>>>();
    k_combine<<<16384, 256>>>();
    dim3 g(OUTD/64, (BB*TT)/64);
    k_outgemm<<<g, 256>>>(out, Wout, bout);
}